// round 7
// baseline (speedup 1.0000x reference)
#include <cuda_runtime.h>
#include <cstdint>

// SpatialTransformer: 2D bilinear warp per depth slice, align_corners=True,
// zero padding. src [B,C,D,H,W] f32, v [B,2,D,H,W] f32, out f32.
// H==W so normalization cancels: ix = x + vx, iy = y + vy.
//
// AoS-staged variant: band of 24 rows staged into SMEM as float4{c0,c1,c2,c3}
// per pixel (4 coalesced LDG.32 + 1 STS.128 per staged pixel). Gather is then
// 4x LDS.128 per output pixel (one per bilinear corner, all channels at once)
// instead of 16x LDS.32 + 16 IADD. Accumulation uses packed fma.rn.f32x2.
// Rows outside the +-4 margin (|vy|>4, ~6e-5) fall back to global __ldg.

constexpr int B = 8, C = 4, D = 32, H = 256, W = 256;
constexpr int HW  = H * W;
constexpr int DHW = D * HW;
constexpr int RB  = 16;                // output rows per block
constexpr int MGN = 4;                 // staged row margin
constexpr int TR  = RB + 2 * MGN;      // 24 staged rows max
constexpr int TPB = 512;               // 16 warps; 1 output row per warp
constexpr int HP  = 4;                 // pixels per half (2 halves = 8 px/thread)
constexpr int NBLK = B * D * (H / RB); // 4096
constexpr size_t SMEM_BYTES = (size_t)TR * W * sizeof(float4);  // 96 KB

union F4U { float4 f; unsigned long long u[2]; };

__device__ __forceinline__ unsigned long long pack2(float k) {
    unsigned long long r;
    asm("mov.b64 %0, {%1, %1};" : "=l"(r) : "f"(k));
    return r;
}
__device__ __forceinline__ unsigned long long mul2(unsigned long long a,
                                                   unsigned long long b) {
    unsigned long long r;
    asm("mul.rn.f32x2 %0, %1, %2;" : "=l"(r) : "l"(a), "l"(b));
    return r;
}
__device__ __forceinline__ void fma2(unsigned long long& d,
                                     unsigned long long a,
                                     unsigned long long b) {
    asm("fma.rn.f32x2 %0, %1, %2, %0;" : "+l"(d) : "l"(a), "l"(b));
}

struct Coords {
    int   o00[HP], o01[HP], o10[HP], o11[HP];
    float k00[HP], k01[HP], k10[HP], k11[HP];
};

__device__ __forceinline__ void compute_coords(
    Coords& cc, const float* __restrict__ vx_row, const float* __restrict__ vy_row,
    int lane, int y, int p0, int r_lo, int r_hi)
{
#pragma unroll
    for (int p = 0; p < HP; p++) {
        const int x = lane + 32 * (p0 + p);
        const float vx = __ldg(vx_row + x);
        const float vy = __ldg(vy_row + x);
        const float ix = (float)x + vx;
        const float iy = (float)y + vy;
        const float x0f = floorf(ix), y0f = floorf(iy);
        const float fx = ix - x0f, fy = iy - y0f;
        const int x0 = (int)x0f, y0 = (int)y0f;
        const int x1 = x0 + 1,   y1 = y0 + 1;

        const float mx0 = (x0 >= 0 && x0 < W) ? 1.0f : 0.0f;
        const float mx1 = (x1 >= 0 && x1 < W) ? 1.0f : 0.0f;
        const float my0 = (y0 >= 0 && y0 < H) ? 1.0f : 0.0f;
        const float my1 = (y1 >= 0 && y1 < H) ? 1.0f : 0.0f;

        const int x0c = min(max(x0, 0), W - 1);
        const int x1c = min(max(x1, 0), W - 1);
        const int y0c = min(max(y0, 0), H - 1);
        const int y1c = min(max(y1, 0), H - 1);

        const float gx0 = 1.0f - fx, gy0 = 1.0f - fy;
        cc.k00[p] = gx0 * gy0 * (mx0 * my0);
        cc.k01[p] = fx  * gy0 * (mx1 * my0);
        cc.k10[p] = gx0 * fy  * (mx0 * my1);
        cc.k11[p] = fx  * fy  * (mx1 * my1);

        if (y0c >= r_lo && y1c < r_hi) {
            const int row0 = (y0c - r_lo) * W, row1 = (y1c - r_lo) * W;
            cc.o00[p] = row0 + x0c; cc.o01[p] = row0 + x1c;
            cc.o10[p] = row1 + x0c; cc.o11[p] = row1 + x1c;
        } else {
            // slow path: encode global plane offsets as ~g (negative)
            cc.o00[p] = ~(y0c * W + x0c); cc.o01[p] = ~(y0c * W + x1c);
            cc.o10[p] = ~(y1c * W + x0c); cc.o11[p] = ~(y1c * W + x1c);
        }
    }
}

__device__ __forceinline__ void gather_store(
    const Coords& cc, const float4* __restrict__ tile,
    const float* __restrict__ splane, float* __restrict__ obase,
    int lane, int p0)
{
#pragma unroll
    for (int p = 0; p < HP; p++) {
        const int x = lane + 32 * (p0 + p);
        if (cc.o00[p] >= 0) {
            F4U s00, s01, s10, s11;
            s00.f = tile[cc.o00[p]];
            s01.f = tile[cc.o01[p]];
            s10.f = tile[cc.o10[p]];
            s11.f = tile[cc.o11[p]];
            const unsigned long long kk00 = pack2(cc.k00[p]);
            const unsigned long long kk01 = pack2(cc.k01[p]);
            const unsigned long long kk10 = pack2(cc.k10[p]);
            const unsigned long long kk11 = pack2(cc.k11[p]);
            unsigned long long lo = mul2(s00.u[0], kk00);
            unsigned long long hi = mul2(s00.u[1], kk00);
            fma2(lo, s01.u[0], kk01); fma2(hi, s01.u[1], kk01);
            fma2(lo, s10.u[0], kk10); fma2(hi, s10.u[1], kk10);
            fma2(lo, s11.u[0], kk11); fma2(hi, s11.u[1], kk11);
            F4U r; r.u[0] = lo; r.u[1] = hi;
            obase[0 * DHW + x] = r.f.x;
            obase[1 * DHW + x] = r.f.y;
            obase[2 * DHW + x] = r.f.z;
            obase[3 * DHW + x] = r.f.w;
        } else {
            const int g00 = ~cc.o00[p], g01 = ~cc.o01[p];
            const int g10 = ~cc.o10[p], g11 = ~cc.o11[p];
#pragma unroll
            for (int c = 0; c < C; c++) {
                const float* sc = splane + (size_t)c * DHW;
                float acc =      __ldg(sc + g00) * cc.k00[p];
                acc = fmaf(__ldg(sc + g01), cc.k01[p], acc);
                acc = fmaf(__ldg(sc + g10), cc.k10[p], acc);
                acc = fmaf(__ldg(sc + g11), cc.k11[p], acc);
                obase[(size_t)c * DHW + x] = acc;
            }
        }
    }
}

__global__ __launch_bounds__(TPB, 2)
void st_kernel(const float* __restrict__ src,
               const float* __restrict__ v,
               float* __restrict__ out)
{
    extern __shared__ float4 tile[];   // [TR * W], AoS over channels

    const int blk = blockIdx.x;
    const int rt  = blk & (H / RB - 1);   // 16 row-tiles
    const int bd  = blk >> 4;
    const int d   = bd & (D - 1);
    const int b   = bd >> 5;
    const int r0  = rt * RB;
    const int r_lo = max(0, r0 - MGN);
    const int r_hi = min(H, r0 + RB + MGN);
    const int nelems = (r_hi - r_lo) * W;

    const float* splane = src + (size_t)(b * C) * DHW + (size_t)d * HW;

    // ---- stage band: 4 coalesced LDG.32 + 1 STS.128 per staged pixel ----
    {
        const float* g0 = splane + r_lo * W;
#pragma unroll 4
        for (int i = threadIdx.x; i < nelems; i += TPB) {
            float4 t;
            t.x = __ldg(g0 + i);
            t.y = __ldg(g0 + DHW + i);
            t.z = __ldg(g0 + 2 * DHW + i);
            t.w = __ldg(g0 + 3 * DHW + i);
            tile[i] = t;
        }
    }

    const int warp = threadIdx.x >> 5, lane = threadIdx.x & 31;
    const int y = r0 + warp;
    const float* vx_row = v + (size_t)(b * 2) * DHW + (size_t)d * HW + y * W;
    const float* vy_row = vx_row + DHW;
    float* obase = out + (size_t)(b * C) * DHW + (size_t)d * HW + y * W;

    // half 1 coords overlap the staging drain / barrier wait
    Coords cc;
    compute_coords(cc, vx_row, vy_row, lane, y, 0, r_lo, r_hi);

    __syncthreads();

    gather_store(cc, tile, splane, obase, lane, 0);
    compute_coords(cc, vx_row, vy_row, lane, y, HP, r_lo, r_hi);
    gather_store(cc, tile, splane, obase, lane, HP);
}

extern "C" void kernel_launch(void* const* d_in, const int* in_sizes, int n_in,
                              void* d_out, int out_size)
{
    const float* src = (const float*)d_in[0];
    const float* v   = (const float*)d_in[1];
    float* out       = (float*)d_out;

    cudaFuncSetAttribute(st_kernel,
                         cudaFuncAttributeMaxDynamicSharedMemorySize,
                         (int)SMEM_BYTES);
    st_kernel<<<NBLK, TPB, SMEM_BYTES>>>(src, v, out);
}

// round 8
// speedup vs baseline: 1.0912x; 1.0912x over previous
#include <cuda_runtime.h>
#include <cstdint>

// SpatialTransformer: 2D bilinear warp per depth slice, align_corners=True,
// zero padding. src [B,C,D,H,W] f32, v [B,2,D,H,W] f32, out f32.
// H==W so normalization cancels: ix = x + vx, iy = y + vy.
//
// Persistent-block double-buffered pipeline: each SM-resident block owns two
// 96KB SoA tile buffers. While gathering tile i it has already TMA-issued
// tile i+1 into the other buffer, hiding the TMA fill latency that bounded
// the R6 version. Gather path identical to R6: 16x LDS.32 per pixel-group,
// bank = x mod 32; rows outside the +-4 margin fall back to global __ldg.

constexpr int B = 8, C = 4, D = 32, H = 256, W = 256;
constexpr int HW  = H * W;
constexpr int DHW = D * HW;
constexpr int RB  = 16;                // output rows per tile
constexpr int MGN = 4;                 // staged row margin (|vy|<=4 fast path)
constexpr int TR  = RB + 2 * MGN;      // 24 staged rows max
constexpr int TPB = 512;               // 16 warps; 1 output row per warp
constexpr int HP  = 4;                 // pixels per half (2 halves = 8 px/thread)
constexpr int TILE_ELEMS = TR * W;     // 6144 floats per channel
constexpr int NTILES = B * D * (H / RB);        // 4096
constexpr int BUF_FLOATS = C * TILE_ELEMS;      // 24576 (96 KB)
constexpr size_t SMEM_BYTES = (size_t)2 * BUF_FLOATS * 4 + 32;

__device__ __forceinline__ uint32_t s2u(const void* p) {
    return (uint32_t)__cvta_generic_to_shared(p);
}

struct Coords {
    int   o00[HP], o01[HP], o10[HP], o11[HP];
    float k00[HP], k01[HP], k10[HP], k11[HP];
};

__device__ __forceinline__ void compute_coords(
    Coords& cc, const float* __restrict__ vx_row, const float* __restrict__ vy_row,
    int lane, int y, int p0, int r_lo, int r_hi)
{
#pragma unroll
    for (int p = 0; p < HP; p++) {
        const int x = lane + 32 * (p0 + p);
        const float vx = __ldg(vx_row + x);
        const float vy = __ldg(vy_row + x);
        const float ix = (float)x + vx;
        const float iy = (float)y + vy;
        const float x0f = floorf(ix), y0f = floorf(iy);
        const float fx = ix - x0f, fy = iy - y0f;
        const int x0 = (int)x0f, y0 = (int)y0f;
        const int x1 = x0 + 1,   y1 = y0 + 1;

        const float mx0 = (x0 >= 0 && x0 < W) ? 1.0f : 0.0f;
        const float mx1 = (x1 >= 0 && x1 < W) ? 1.0f : 0.0f;
        const float my0 = (y0 >= 0 && y0 < H) ? 1.0f : 0.0f;
        const float my1 = (y1 >= 0 && y1 < H) ? 1.0f : 0.0f;

        const int x0c = min(max(x0, 0), W - 1);
        const int x1c = min(max(x1, 0), W - 1);
        const int y0c = min(max(y0, 0), H - 1);
        const int y1c = min(max(y1, 0), H - 1);

        const float gx0 = 1.0f - fx, gy0 = 1.0f - fy;
        cc.k00[p] = gx0 * gy0 * (mx0 * my0);
        cc.k01[p] = fx  * gy0 * (mx1 * my0);
        cc.k10[p] = gx0 * fy  * (mx0 * my1);
        cc.k11[p] = fx  * fy  * (mx1 * my1);

        if (y0c >= r_lo && y1c < r_hi) {
            const int row0 = (y0c - r_lo) * W, row1 = (y1c - r_lo) * W;
            cc.o00[p] = row0 + x0c; cc.o01[p] = row0 + x1c;
            cc.o10[p] = row1 + x0c; cc.o11[p] = row1 + x1c;
        } else {
            // slow path: encode global plane offsets as ~g (negative)
            cc.o00[p] = ~(y0c * W + x0c); cc.o01[p] = ~(y0c * W + x1c);
            cc.o10[p] = ~(y1c * W + x0c); cc.o11[p] = ~(y1c * W + x1c);
        }
    }
}

__device__ __forceinline__ void gather_store(
    const Coords& cc, const float* __restrict__ tile,
    const float* __restrict__ splane, float* __restrict__ obase,
    int lane, int p0)
{
#pragma unroll
    for (int p = 0; p < HP; p++) {
        const int x = lane + 32 * (p0 + p);
        if (cc.o00[p] >= 0) {
#pragma unroll
            for (int c = 0; c < C; c++) {
                const float* tc = tile + c * TILE_ELEMS;
                float acc =      tc[cc.o00[p]] * cc.k00[p];
                acc = fmaf(tc[cc.o01[p]], cc.k01[p], acc);
                acc = fmaf(tc[cc.o10[p]], cc.k10[p], acc);
                acc = fmaf(tc[cc.o11[p]], cc.k11[p], acc);
                obase[(size_t)c * DHW + x] = acc;
            }
        } else {
            const int g00 = ~cc.o00[p], g01 = ~cc.o01[p];
            const int g10 = ~cc.o10[p], g11 = ~cc.o11[p];
#pragma unroll
            for (int c = 0; c < C; c++) {
                const float* sc = splane + (size_t)c * DHW;
                float acc =      __ldg(sc + g00) * cc.k00[p];
                acc = fmaf(__ldg(sc + g01), cc.k01[p], acc);
                acc = fmaf(__ldg(sc + g10), cc.k10[p], acc);
                acc = fmaf(__ldg(sc + g11), cc.k11[p], acc);
                obase[(size_t)c * DHW + x] = acc;
            }
        }
    }
}

// Issue the 4-channel TMA band load for tile tt into SMEM buffer buf.
__device__ __forceinline__ void issue_tile(
    const float* __restrict__ src, int tt, uint32_t mb, const float* buf)
{
    const int rt = tt & (H / RB - 1);
    const int bd = tt >> 4;
    const int d  = bd & (D - 1);
    const int b  = bd >> 5;
    const int r0 = rt * RB;
    const int r_lo = max(0, r0 - MGN);
    const int r_hi = min(H, r0 + RB + MGN);
    const int bytes = (r_hi - r_lo) * W * 4;
    const float* splane = src + (size_t)(b * C) * DHW + (size_t)d * HW;

    asm volatile("mbarrier.arrive.expect_tx.shared.b64 _, [%0], %1;"
                 :: "r"(mb), "r"(bytes * C) : "memory");
#pragma unroll
    for (int c = 0; c < C; c++) {
        const uint32_t dst = s2u(buf + c * TILE_ELEMS);
        const float* gsrc = splane + (size_t)c * DHW + r_lo * W;
        asm volatile(
            "cp.async.bulk.shared::cluster.global.mbarrier::complete_tx::bytes "
            "[%0], [%1], %2, [%3];"
            :: "r"(dst), "l"(gsrc), "r"(bytes), "r"(mb) : "memory");
    }
}

__device__ __forceinline__ void wait_full(uint32_t mb, int phase)
{
    uint32_t done;
    do {
        asm volatile(
            "{.reg .pred p; mbarrier.try_wait.parity.acquire.cta.shared::cta.b64 "
            "p, [%1], %2; selp.b32 %0, 1, 0, p;}"
            : "=r"(done) : "r"(mb), "r"(phase) : "memory");
    } while (!done);
}

__global__ __launch_bounds__(TPB, 1)
void st_kernel(const float* __restrict__ src,
               const float* __restrict__ v,
               float* __restrict__ out)
{
    extern __shared__ float smem[];
    float* buf0 = smem;
    float* buf1 = smem + BUF_FLOATS;
    const uint32_t mb0 = s2u(smem + 2 * BUF_FLOATS);
    const uint32_t mb1 = mb0 + 8;

    if (threadIdx.x == 0) {
        asm volatile("mbarrier.init.shared.b64 [%0], 1;" :: "r"(mb0) : "memory");
        asm volatile("mbarrier.init.shared.b64 [%0], 1;" :: "r"(mb1) : "memory");
    }
    __syncthreads();

    int tt = blockIdx.x;
    if (tt < NTILES && threadIdx.x == 0) issue_tile(src, tt, mb0, buf0);

    const int warp = threadIdx.x >> 5, lane = threadIdx.x & 31;
    int cur = 0, ph0 = 0, ph1 = 0;

    for (; tt < NTILES; tt += gridDim.x) {
        const int ntt = tt + gridDim.x;
        if (ntt < NTILES && threadIdx.x == 0) {
            issue_tile(src, ntt, cur ? mb0 : mb1, cur ? buf0 : buf1);
        }

        // decode current tile
        const int rt = tt & (H / RB - 1);
        const int bd = tt >> 4;
        const int d  = bd & (D - 1);
        const int b  = bd >> 5;
        const int r0 = rt * RB;
        const int r_lo = max(0, r0 - MGN);
        const int r_hi = min(H, r0 + RB + MGN);

        const float* splane = src + (size_t)(b * C) * DHW + (size_t)d * HW;
        const int y = r0 + warp;
        const float* vx_row = v + (size_t)(b * 2) * DHW + (size_t)d * HW + y * W;
        const float* vy_row = vx_row + DHW;
        float* obase = out + (size_t)(b * C) * DHW + (size_t)d * HW + y * W;
        const float* tile = cur ? buf1 : buf0;

        // coords half 1 overlaps the in-flight TMA
        Coords cc;
        compute_coords(cc, vx_row, vy_row, lane, y, 0, r_lo, r_hi);

        if (cur) { wait_full(mb1, ph1); ph1 ^= 1; }
        else     { wait_full(mb0, ph0); ph0 ^= 1; }

        gather_store(cc, tile, splane, obase, lane, 0);
        compute_coords(cc, vx_row, vy_row, lane, y, HP, r_lo, r_hi);
        gather_store(cc, tile, splane, obase, lane, HP);

        __syncthreads();   // all reads of `tile` done -> buffer reusable
        cur ^= 1;
    }
}

extern "C" void kernel_launch(void* const* d_in, const int* in_sizes, int n_in,
                              void* d_out, int out_size)
{
    const float* src = (const float*)d_in[0];
    const float* v   = (const float*)d_in[1];
    float* out       = (float*)d_out;

    int nsm = 148;
    cudaDeviceGetAttribute(&nsm, cudaDevAttrMultiProcessorCount, 0);
    if (nsm > NTILES) nsm = NTILES;

    cudaFuncSetAttribute(st_kernel,
                         cudaFuncAttributeMaxDynamicSharedMemorySize,
                         (int)SMEM_BYTES);
    st_kernel<<<nsm, TPB, SMEM_BYTES>>>(src, v, out);
}

// round 9
// speedup vs baseline: 1.2120x; 1.1107x over previous
#include <cuda_runtime.h>
#include <cstdint>

// SpatialTransformer: 2D bilinear warp per depth slice, align_corners=True,
// zero padding. src [B,C,D,H,W] f32, v [B,2,D,H,W] f32, out f32.
// H==W so normalization cancels: ix = x + vx, iy = y + vy.
//
// Double-buffered TMA pipeline x 2 blocks/SM:
//   RB=8 output rows/tile, +-3 margin -> 14 staged rows = 56KB SoA buffer.
//   Each 512-thread block owns 2 buffers (112KB); 2 blocks/SM = 224KB SMEM,
//   32 warps/SM. Block TMA-issues tile i+1 into its idle buffer before
//   gathering tile i (fill latency hidden); the sibling block absorbs
//   __syncthreads bubbles (R8's single-block pipeline lacked this).
// Gather: 16x LDS.32 per pixel-group, bank = x mod 32. Rows outside the
// +-3 margin (|vy|>3, ~0.3%) fall back to global __ldg.

constexpr int B = 8, C = 4, D = 32, H = 256, W = 256;
constexpr int HW  = H * W;
constexpr int DHW = D * HW;
constexpr int RB  = 8;                 // output rows per tile
constexpr int MGN = 3;                 // staged row margin
constexpr int TR  = RB + 2 * MGN;      // 14 staged rows max
constexpr int TPB = 512;               // 16 warps; warp = half row; 4 px/thread
constexpr int HP  = 4;                 // pixels per thread
constexpr int TILE_ELEMS = TR * W;     // 3584 floats per channel
constexpr int BUF_FLOATS = C * TILE_ELEMS;       // 14336 (56 KB)
constexpr int NTILES = B * D * (H / RB);         // 8192
constexpr size_t SMEM_BYTES = (size_t)2 * BUF_FLOATS * 4 + 32;  // ~112 KB

__device__ __forceinline__ uint32_t s2u(const void* p) {
    return (uint32_t)__cvta_generic_to_shared(p);
}

struct Coords {
    int   o00[HP], o01[HP], o10[HP], o11[HP];
    float k00[HP], k01[HP], k10[HP], k11[HP];
};

__device__ __forceinline__ void compute_coords(
    Coords& cc, const float* __restrict__ vx_row, const float* __restrict__ vy_row,
    int xbase, int y, int r_lo, int r_hi)
{
#pragma unroll
    for (int p = 0; p < HP; p++) {
        const int x = xbase + 32 * p;
        const float vx = __ldg(vx_row + x);
        const float vy = __ldg(vy_row + x);
        const float ix = (float)x + vx;
        const float iy = (float)y + vy;
        const float x0f = floorf(ix), y0f = floorf(iy);
        const float fx = ix - x0f, fy = iy - y0f;
        const int x0 = (int)x0f, y0 = (int)y0f;
        const int x1 = x0 + 1,   y1 = y0 + 1;

        const float mx0 = (x0 >= 0 && x0 < W) ? 1.0f : 0.0f;
        const float mx1 = (x1 >= 0 && x1 < W) ? 1.0f : 0.0f;
        const float my0 = (y0 >= 0 && y0 < H) ? 1.0f : 0.0f;
        const float my1 = (y1 >= 0 && y1 < H) ? 1.0f : 0.0f;

        const int x0c = min(max(x0, 0), W - 1);
        const int x1c = min(max(x1, 0), W - 1);
        const int y0c = min(max(y0, 0), H - 1);
        const int y1c = min(max(y1, 0), H - 1);

        const float gx0 = 1.0f - fx, gy0 = 1.0f - fy;
        cc.k00[p] = gx0 * gy0 * (mx0 * my0);
        cc.k01[p] = fx  * gy0 * (mx1 * my0);
        cc.k10[p] = gx0 * fy  * (mx0 * my1);
        cc.k11[p] = fx  * fy  * (mx1 * my1);

        if (y0c >= r_lo && y1c < r_hi) {
            const int row0 = (y0c - r_lo) * W, row1 = (y1c - r_lo) * W;
            cc.o00[p] = row0 + x0c; cc.o01[p] = row0 + x1c;
            cc.o10[p] = row1 + x0c; cc.o11[p] = row1 + x1c;
        } else {
            // slow path: encode global plane offsets as ~g (negative)
            cc.o00[p] = ~(y0c * W + x0c); cc.o01[p] = ~(y0c * W + x1c);
            cc.o10[p] = ~(y1c * W + x0c); cc.o11[p] = ~(y1c * W + x1c);
        }
    }
}

__device__ __forceinline__ void gather_store(
    const Coords& cc, const float* __restrict__ tile,
    const float* __restrict__ splane, float* __restrict__ obase,
    int xbase)
{
#pragma unroll
    for (int p = 0; p < HP; p++) {
        const int x = xbase + 32 * p;
        if (cc.o00[p] >= 0) {
#pragma unroll
            for (int c = 0; c < C; c++) {
                const float* tc = tile + c * TILE_ELEMS;
                float acc =      tc[cc.o00[p]] * cc.k00[p];
                acc = fmaf(tc[cc.o01[p]], cc.k01[p], acc);
                acc = fmaf(tc[cc.o10[p]], cc.k10[p], acc);
                acc = fmaf(tc[cc.o11[p]], cc.k11[p], acc);
                obase[(size_t)c * DHW + x] = acc;
            }
        } else {
            const int g00 = ~cc.o00[p], g01 = ~cc.o01[p];
            const int g10 = ~cc.o10[p], g11 = ~cc.o11[p];
#pragma unroll
            for (int c = 0; c < C; c++) {
                const float* sc = splane + (size_t)c * DHW;
                float acc =      __ldg(sc + g00) * cc.k00[p];
                acc = fmaf(__ldg(sc + g01), cc.k01[p], acc);
                acc = fmaf(__ldg(sc + g10), cc.k10[p], acc);
                acc = fmaf(__ldg(sc + g11), cc.k11[p], acc);
                obase[(size_t)c * DHW + x] = acc;
            }
        }
    }
}

// Issue the 4-channel TMA band load for tile tt into SMEM buffer buf.
__device__ __forceinline__ void issue_tile(
    const float* __restrict__ src, int tt, uint32_t mb, const float* buf)
{
    const int rt = tt & (H / RB - 1);   // 32 row-tiles
    const int bd = tt >> 5;
    const int d  = bd & (D - 1);
    const int b  = bd >> 5;
    const int r0 = rt * RB;
    const int r_lo = max(0, r0 - MGN);
    const int r_hi = min(H, r0 + RB + MGN);
    const int bytes = (r_hi - r_lo) * W * 4;
    const float* splane = src + (size_t)(b * C) * DHW + (size_t)d * HW;

    asm volatile("mbarrier.arrive.expect_tx.shared.b64 _, [%0], %1;"
                 :: "r"(mb), "r"(bytes * C) : "memory");
#pragma unroll
    for (int c = 0; c < C; c++) {
        const uint32_t dst = s2u(buf + c * TILE_ELEMS);
        const float* gsrc = splane + (size_t)c * DHW + r_lo * W;
        asm volatile(
            "cp.async.bulk.shared::cluster.global.mbarrier::complete_tx::bytes "
            "[%0], [%1], %2, [%3];"
            :: "r"(dst), "l"(gsrc), "r"(bytes), "r"(mb) : "memory");
    }
}

__device__ __forceinline__ void wait_full(uint32_t mb, int phase)
{
    uint32_t done;
    do {
        asm volatile(
            "{.reg .pred p; mbarrier.try_wait.parity.acquire.cta.shared::cta.b64 "
            "p, [%1], %2; selp.b32 %0, 1, 0, p;}"
            : "=r"(done) : "r"(mb), "r"(phase) : "memory");
    } while (!done);
}

__global__ __launch_bounds__(TPB, 2)
void st_kernel(const float* __restrict__ src,
               const float* __restrict__ v,
               float* __restrict__ out)
{
    extern __shared__ float smem[];
    float* buf0 = smem;
    float* buf1 = smem + BUF_FLOATS;
    const uint32_t mb0 = s2u(smem + 2 * BUF_FLOATS);
    const uint32_t mb1 = mb0 + 8;

    if (threadIdx.x == 0) {
        asm volatile("mbarrier.init.shared.b64 [%0], 1;" :: "r"(mb0) : "memory");
        asm volatile("mbarrier.init.shared.b64 [%0], 1;" :: "r"(mb1) : "memory");
    }
    __syncthreads();

    int tt = blockIdx.x;
    if (tt < NTILES && threadIdx.x == 0) issue_tile(src, tt, mb0, buf0);

    const int warp  = threadIdx.x >> 5, lane = threadIdx.x & 31;
    const int row_i = warp >> 1;                 // 0..7
    const int xbase = ((warp & 1) << 7) + lane;  // 0..255
    int cur = 0, ph0 = 0, ph1 = 0;

    for (; tt < NTILES; tt += gridDim.x) {
        const int ntt = tt + gridDim.x;
        if (ntt < NTILES && threadIdx.x == 0) {
            issue_tile(src, ntt, cur ? mb0 : mb1, cur ? buf0 : buf1);
        }

        // decode current tile
        const int rt = tt & (H / RB - 1);
        const int bd = tt >> 5;
        const int d  = bd & (D - 1);
        const int b  = bd >> 5;
        const int r0 = rt * RB;
        const int r_lo = max(0, r0 - MGN);
        const int r_hi = min(H, r0 + RB + MGN);

        const float* splane = src + (size_t)(b * C) * DHW + (size_t)d * HW;
        const int y = r0 + row_i;
        const float* vx_row = v + (size_t)(b * 2) * DHW + (size_t)d * HW + y * W;
        const float* vy_row = vx_row + DHW;
        float* obase = out + (size_t)(b * C) * DHW + (size_t)d * HW + y * W;
        const float* tile = cur ? buf1 : buf0;

        // coords overlap the in-flight TMA
        Coords cc;
        compute_coords(cc, vx_row, vy_row, xbase, y, r_lo, r_hi);

        if (cur) { wait_full(mb1, ph1); ph1 ^= 1; }
        else     { wait_full(mb0, ph0); ph0 ^= 1; }

        gather_store(cc, tile, splane, obase, xbase);

        __syncthreads();   // all reads of `tile` done -> buffer reusable
        cur ^= 1;
    }
}

extern "C" void kernel_launch(void* const* d_in, const int* in_sizes, int n_in,
                              void* d_out, int out_size)
{
    const float* src = (const float*)d_in[0];
    const float* v   = (const float*)d_in[1];
    float* out       = (float*)d_out;

    int nsm = 148;
    cudaDeviceGetAttribute(&nsm, cudaDevAttrMultiProcessorCount, 0);
    int nblk = 2 * nsm;
    if (nblk > NTILES) nblk = NTILES;

    cudaFuncSetAttribute(st_kernel,
                         cudaFuncAttributeMaxDynamicSharedMemorySize,
                         (int)SMEM_BYTES);
    st_kernel<<<nblk, TPB, SMEM_BYTES>>>(src, v, out);
}

// round 10
// speedup vs baseline: 1.3009x; 1.0734x over previous
#include <cuda_runtime.h>
#include <cstdint>

// SpatialTransformer: 2D bilinear warp per depth slice, align_corners=True,
// zero padding. src [B,C,D,H,W] f32, v [B,2,D,H,W] f32, out f32.
// H==W so normalization cancels: ix = x + vx, iy = y + vy.
//
// R6 structure (one-shot block: TMA band load -> coords overlap -> wait ->
// LDS gather), shrunk so FOUR independent blocks co-reside per SM:
//   RB=8 output rows, staged rows r0-3 .. r0+9 (TR=13, asymmetric margin)
//   -> 53KB SoA tile; 4 x 256-thread blocks/SM (64 regs = full RF).
// While one block waits on its TMA, three others gather -> latency absorbed
// by block-level parallelism instead of the failed R7-R9 intra-block pipelines.
// Out-of-band rows (~0.3% of pixels) fall back to global __ldg.

constexpr int B = 8, C = 4, D = 32, H = 256, W = 256;
constexpr int HW  = H * W;
constexpr int DHW = D * HW;
constexpr int RB  = 8;                 // output rows per block
constexpr int MLO = 3, MHI = 2;        // staged margin below/above
constexpr int TR  = RB + MLO + MHI;    // 13 staged rows max
constexpr int TPB = 256;               // 8 warps; 1 output row per warp
constexpr int HP  = 4;                 // pixels per half (2 halves = 8 px/thread)
constexpr int TILE_ELEMS = TR * W;     // 3328 floats per channel
constexpr int NBLK = B * D * (H / RB); // 8192
constexpr size_t SMEM_BYTES = (size_t)C * TILE_ELEMS * 4 + 16;  // 53264 B

__device__ __forceinline__ uint32_t s2u(const void* p) {
    return (uint32_t)__cvta_generic_to_shared(p);
}

struct Coords {
    int   o00[HP], o01[HP], o10[HP], o11[HP];
    float k00[HP], k01[HP], k10[HP], k11[HP];
};

__device__ __forceinline__ void compute_coords(
    Coords& cc, const float* __restrict__ vx_row, const float* __restrict__ vy_row,
    int lane, int y, int p0, int r_lo, int r_hi)
{
#pragma unroll
    for (int p = 0; p < HP; p++) {
        const int x = lane + 32 * (p0 + p);
        const float vx = __ldg(vx_row + x);
        const float vy = __ldg(vy_row + x);
        const float ix = (float)x + vx;
        const float iy = (float)y + vy;
        const float x0f = floorf(ix), y0f = floorf(iy);
        const float fx = ix - x0f, fy = iy - y0f;
        const int x0 = (int)x0f, y0 = (int)y0f;
        const int x1 = x0 + 1,   y1 = y0 + 1;

        const float mx0 = (x0 >= 0 && x0 < W) ? 1.0f : 0.0f;
        const float mx1 = (x1 >= 0 && x1 < W) ? 1.0f : 0.0f;
        const float my0 = (y0 >= 0 && y0 < H) ? 1.0f : 0.0f;
        const float my1 = (y1 >= 0 && y1 < H) ? 1.0f : 0.0f;

        const int x0c = min(max(x0, 0), W - 1);
        const int x1c = min(max(x1, 0), W - 1);
        const int y0c = min(max(y0, 0), H - 1);
        const int y1c = min(max(y1, 0), H - 1);

        const float gx0 = 1.0f - fx, gy0 = 1.0f - fy;
        cc.k00[p] = gx0 * gy0 * (mx0 * my0);
        cc.k01[p] = fx  * gy0 * (mx1 * my0);
        cc.k10[p] = gx0 * fy  * (mx0 * my1);
        cc.k11[p] = fx  * fy  * (mx1 * my1);

        if (y0c >= r_lo && y1c < r_hi) {
            const int row0 = (y0c - r_lo) * W, row1 = (y1c - r_lo) * W;
            cc.o00[p] = row0 + x0c; cc.o01[p] = row0 + x1c;
            cc.o10[p] = row1 + x0c; cc.o11[p] = row1 + x1c;
        } else {
            // slow path: encode global plane offsets as ~g (negative)
            cc.o00[p] = ~(y0c * W + x0c); cc.o01[p] = ~(y0c * W + x1c);
            cc.o10[p] = ~(y1c * W + x0c); cc.o11[p] = ~(y1c * W + x1c);
        }
    }
}

__device__ __forceinline__ void gather_store(
    const Coords& cc, const float* __restrict__ tile,
    const float* __restrict__ splane, float* __restrict__ obase,
    int lane, int p0)
{
#pragma unroll
    for (int p = 0; p < HP; p++) {
        const int x = lane + 32 * (p0 + p);
        if (cc.o00[p] >= 0) {
#pragma unroll
            for (int c = 0; c < C; c++) {
                const float* tc = tile + c * TILE_ELEMS;
                float acc =      tc[cc.o00[p]] * cc.k00[p];
                acc = fmaf(tc[cc.o01[p]], cc.k01[p], acc);
                acc = fmaf(tc[cc.o10[p]], cc.k10[p], acc);
                acc = fmaf(tc[cc.o11[p]], cc.k11[p], acc);
                obase[(size_t)c * DHW + x] = acc;
            }
        } else {
            const int g00 = ~cc.o00[p], g01 = ~cc.o01[p];
            const int g10 = ~cc.o10[p], g11 = ~cc.o11[p];
#pragma unroll
            for (int c = 0; c < C; c++) {
                const float* sc = splane + (size_t)c * DHW;
                float acc =      __ldg(sc + g00) * cc.k00[p];
                acc = fmaf(__ldg(sc + g01), cc.k01[p], acc);
                acc = fmaf(__ldg(sc + g10), cc.k10[p], acc);
                acc = fmaf(__ldg(sc + g11), cc.k11[p], acc);
                obase[(size_t)c * DHW + x] = acc;
            }
        }
    }
}

__global__ __launch_bounds__(TPB, 4)
void st_kernel(const float* __restrict__ src,
               const float* __restrict__ v,
               float* __restrict__ out)
{
    extern __shared__ float smem[];
    float* tile = smem;  // [C][TILE_ELEMS]
    unsigned long long* mbar = (unsigned long long*)(smem + C * TILE_ELEMS);

    const int blk = blockIdx.x;
    const int rt  = blk & (H / RB - 1);   // 32 row-tiles
    const int bd  = blk >> 5;
    const int d   = bd & (D - 1);
    const int b   = bd >> 5;
    const int r0  = rt * RB;
    const int r_lo = max(0, r0 - MLO);
    const int r_hi = min(H, r0 + RB + MHI);
    const int nrows = r_hi - r_lo;

    const float* splane = src + (size_t)(b * C) * DHW + (size_t)d * HW;

    const uint32_t mb = s2u(mbar);
    if (threadIdx.x == 0) {
        asm volatile("mbarrier.init.shared.b64 [%0], 1;" :: "r"(mb) : "memory");
    }
    __syncthreads();
    if (threadIdx.x == 0) {
        const int bytes = nrows * W * 4;
        asm volatile("mbarrier.arrive.expect_tx.shared.b64 _, [%0], %1;"
                     :: "r"(mb), "r"(bytes * C) : "memory");
#pragma unroll
        for (int c = 0; c < C; c++) {
            const uint32_t dst = s2u(tile + c * TILE_ELEMS);
            const float* gsrc = splane + (size_t)c * DHW + r_lo * W;
            asm volatile(
                "cp.async.bulk.shared::cluster.global.mbarrier::complete_tx::bytes "
                "[%0], [%1], %2, [%3];"
                :: "r"(dst), "l"(gsrc), "r"(bytes), "r"(mb) : "memory");
        }
    }

    const int warp = threadIdx.x >> 5, lane = threadIdx.x & 31;
    const int y = r0 + warp;
    const float* vx_row = v + (size_t)(b * 2) * DHW + (size_t)d * HW + y * W;
    const float* vy_row = vx_row + DHW;
    float* obase = out + (size_t)(b * C) * DHW + (size_t)d * HW + y * W;

    // half 1 coords overlap the TMA
    Coords cc;
    compute_coords(cc, vx_row, vy_row, lane, y, 0, r_lo, r_hi);

    // wait for TMA tiles
    {
        uint32_t done;
        do {
            asm volatile(
                "{.reg .pred p; mbarrier.try_wait.parity.acquire.cta.shared::cta.b64 "
                "p, [%1], %2; selp.b32 %0, 1, 0, p;}"
                : "=r"(done) : "r"(mb), "r"(0u) : "memory");
        } while (!done);
    }

    gather_store(cc, tile, splane, obase, lane, 0);
    compute_coords(cc, vx_row, vy_row, lane, y, HP, r_lo, r_hi);
    gather_store(cc, tile, splane, obase, lane, HP);
}

extern "C" void kernel_launch(void* const* d_in, const int* in_sizes, int n_in,
                              void* d_out, int out_size)
{
    const float* src = (const float*)d_in[0];
    const float* v   = (const float*)d_in[1];
    float* out       = (float*)d_out;

    cudaFuncSetAttribute(st_kernel,
                         cudaFuncAttributeMaxDynamicSharedMemorySize,
                         (int)SMEM_BYTES);
    st_kernel<<<NBLK, TPB, SMEM_BYTES>>>(src, v, out);
}